// round 1
// baseline (speedup 1.0000x reference)
#include <cuda_runtime.h>
#include <cstdint>

#define SEQ     8
#define HDIM    512
#define HOUT    256
#define LN_EPS  1e-5f
#define MAX_ROWS 65536

typedef unsigned long long ull;

// Scratch for the fused (node + pooled) vectors, [N, 512] fp32.
__device__ float g_fused[(size_t)MAX_ROWS * HDIM];

__device__ __forceinline__ float warp_sum(float v) {
    #pragma unroll
    for (int o = 16; o; o >>= 1) v += __shfl_xor_sync(0xffffffffu, v, o);
    return v;
}

__device__ __forceinline__ ull pack_dup(float a) {
    ull r;
    unsigned u = __float_as_uint(a);
    asm("mov.b64 %0, {%1, %1};" : "=l"(r) : "r"(u));
    return r;
}
__device__ __forceinline__ ull fma2(ull a, ull b, ull c) {
    ull d;
    asm("fma.rn.f32x2 %0, %1, %2, %3;" : "=l"(d) : "l"(a), "l"(b), "l"(c));
    return d;
}
__device__ __forceinline__ float2 unpack2(ull v) {
    unsigned lo, hi;
    asm("mov.b64 {%0, %1}, %2;" : "=r"(lo), "=r"(hi) : "l"(v));
    return make_float2(__uint_as_float(lo), __uint_as_float(hi));
}

// ---------------------------------------------------------------------------
// Kernel A: LayerNorm (8 positions) + attention softmax pooling -> fused vec
// One CTA per row; warp w handles seq position w.
// ---------------------------------------------------------------------------
__global__ __launch_bounds__(256) void ln_attn_kernel(
    const float* __restrict__ x,       // [N, 8, 512]
    const float* __restrict__ gamma,   // [512]
    const float* __restrict__ beta,    // [512]
    const float* __restrict__ attnW)   // [1024]
{
    __shared__ float s_y[SEQ][HDIM];
    __shared__ float s_logit[SEQ];

    const int row  = blockIdx.x;
    const int w    = threadIdx.x >> 5;
    const int lane = threadIdx.x & 31;

    const float4* xp = reinterpret_cast<const float4*>(
        x + (size_t)row * SEQ * HDIM + (size_t)w * HDIM);

    // Load 512 floats per warp (16 per lane), accumulate LN stats.
    float4 v[4];
    float sum = 0.f, sq = 0.f;
    #pragma unroll
    for (int i = 0; i < 4; i++) {
        v[i] = xp[lane + i * 32];
        sum += v[i].x + v[i].y + v[i].z + v[i].w;
        sq  += v[i].x * v[i].x + v[i].y * v[i].y + v[i].z * v[i].z + v[i].w * v[i].w;
    }
    sum = warp_sum(sum);
    sq  = warp_sum(sq);
    const float mean = sum * (1.f / HDIM);
    const float var  = sq * (1.f / HDIM) - mean * mean;
    const float rstd = rsqrtf(var + LN_EPS);

    // Normalize + gamma/beta; fused attention-logit dot.
    // w==0 -> node (dot with W_t = attnW[0:512]); w>=1 -> neighbor (W_n = attnW[512:1024]).
    const float4* gp = reinterpret_cast<const float4*>(gamma);
    const float4* bp = reinterpret_cast<const float4*>(beta);
    const float4* wp = reinterpret_cast<const float4*>(attnW + (w == 0 ? 0 : HDIM));

    float dot = 0.f;
    #pragma unroll
    for (int i = 0; i < 4; i++) {
        const int idx = lane + i * 32;
        const float4 g  = __ldg(gp + idx);
        const float4 bb = __ldg(bp + idx);
        const float4 ww = __ldg(wp + idx);
        float4 y;
        y.x = (v[i].x - mean) * rstd * g.x + bb.x;
        y.y = (v[i].y - mean) * rstd * g.y + bb.y;
        y.z = (v[i].z - mean) * rstd * g.z + bb.z;
        y.w = (v[i].w - mean) * rstd * g.w + bb.w;
        dot += y.x * ww.x + y.y * ww.y + y.z * ww.z + y.w * ww.w;
        reinterpret_cast<float4*>(&s_y[w][0])[idx] = y;
    }
    dot = warp_sum(dot);
    if (lane == 0) s_logit[w] = dot;
    __syncthreads();

    // Softmax over the 7 neighbor logits. The (node . W_t + attn_b) term is a
    // per-row constant added to every logit -> cancels in softmax exactly.
    float l[7];
    float m = -1e30f;
    #pragma unroll
    for (int j = 0; j < 7; j++) { l[j] = s_logit[j + 1]; m = fmaxf(m, l[j]); }
    float s = 0.f;
    #pragma unroll
    for (int j = 0; j < 7; j++) { l[j] = __expf(l[j] - m); s += l[j]; }
    const float inv = 1.f / s;

    // fused[c] = node[c] + sum_j a_j * neighbor_j[c]; 2 columns per thread.
    const int c = threadIdx.x * 2;
    float2 acc = *reinterpret_cast<const float2*>(&s_y[0][c]);
    #pragma unroll
    for (int j = 0; j < 7; j++) {
        const float a = l[j] * inv;
        const float2 yv = *reinterpret_cast<const float2*>(&s_y[j + 1][c]);
        acc.x += a * yv.x;
        acc.y += a * yv.y;
    }
    *reinterpret_cast<float2*>(&g_fused[(size_t)row * HDIM + c]) = acc;
}

// ---------------------------------------------------------------------------
// Kernel B: C = relu(A @ B + bias), A=[M,512] (g_fused), B=[512,256], C=[M,256]
// 128x128x16 tiles, 256 threads, 8x8 microtile, f32x2 packed FMA.
// ---------------------------------------------------------------------------
#define BM 128
#define BN 128
#define BK 16
#define TM 8
#define TN 8

__global__ __launch_bounds__(256) void gemm_relu_kernel(
    const float* __restrict__ B,     // [512, 256] row-major
    const float* __restrict__ bias,  // [256]
    float* __restrict__ C)           // [M, 256] row-major
{
    __shared__ float As[BK][BM + 4];   // transposed A tile, padded vs bank conflicts
    __shared__ float Bs[BK][BN];

    const int bx = blockIdx.x;   // N tile (0..1)
    const int by = blockIdx.y;   // M tile
    const int t  = threadIdx.x;
    const int tx = t & 15;       // 0..15 -> 8 cols each
    const int ty = t >> 4;       // 0..15 -> 8 rows each

    const float* Ag = g_fused + (size_t)by * BM * HDIM;
    const float* Bg = B + bx * BN;

    // Global-load index split
    const int a_row = t >> 2;          // 0..63  (two passes: +0, +64)
    const int a_col = (t & 3) * 4;     // 0,4,8,12
    const int b_row = t >> 5;          // 0..7   (two passes: +0, +8)
    const int b_col = (t & 31) * 4;    // 0..124

    ull acc[TM][TN / 2];
    #pragma unroll
    for (int i = 0; i < TM; i++)
        #pragma unroll
        for (int j = 0; j < TN / 2; j++) acc[i][j] = 0ull;

    for (int k0 = 0; k0 < HDIM; k0 += BK) {
        #pragma unroll
        for (int r = 0; r < 2; r++) {
            const float4 av = *reinterpret_cast<const float4*>(
                Ag + (size_t)(a_row + r * 64) * HDIM + k0 + a_col);
            As[a_col + 0][a_row + r * 64] = av.x;
            As[a_col + 1][a_row + r * 64] = av.y;
            As[a_col + 2][a_row + r * 64] = av.z;
            As[a_col + 3][a_row + r * 64] = av.w;
        }
        #pragma unroll
        for (int r = 0; r < 2; r++) {
            const float4 bv = *reinterpret_cast<const float4*>(
                Bg + (size_t)(k0 + b_row + r * 8) * HOUT + b_col);
            *reinterpret_cast<float4*>(&Bs[b_row + r * 8][b_col]) = bv;
        }
        __syncthreads();

        #pragma unroll
        for (int kk = 0; kk < BK; kk++) {
            const float4 a0 = *reinterpret_cast<const float4*>(&As[kk][ty * TM]);
            const float4 a1 = *reinterpret_cast<const float4*>(&As[kk][ty * TM + 4]);
            const ulonglong2 b0 = *reinterpret_cast<const ulonglong2*>(&Bs[kk][tx * TN]);
            const ulonglong2 b1 = *reinterpret_cast<const ulonglong2*>(&Bs[kk][tx * TN + 4]);
            const ull bpr[4] = {b0.x, b0.y, b1.x, b1.y};
            const float av[8] = {a0.x, a0.y, a0.z, a0.w, a1.x, a1.y, a1.z, a1.w};
            #pragma unroll
            for (int i = 0; i < TM; i++) {
                const ull ap = pack_dup(av[i]);
                #pragma unroll
                for (int j = 0; j < TN / 2; j++)
                    acc[i][j] = fma2(ap, bpr[j], acc[i][j]);
            }
        }
        __syncthreads();
    }

    // Epilogue: bias + relu, vectorized stores.
    const int row0 = by * BM + ty * TM;
    const int col0 = bx * BN + tx * TN;
    const float4 bb0 = *reinterpret_cast<const float4*>(&bias[col0]);
    const float4 bb1 = *reinterpret_cast<const float4*>(&bias[col0 + 4]);
    #pragma unroll
    for (int i = 0; i < TM; i++) {
        const float2 p0 = unpack2(acc[i][0]);
        const float2 p1 = unpack2(acc[i][1]);
        const float2 p2 = unpack2(acc[i][2]);
        const float2 p3 = unpack2(acc[i][3]);
        float4 o0, o1;
        o0.x = fmaxf(p0.x + bb0.x, 0.f);
        o0.y = fmaxf(p0.y + bb0.y, 0.f);
        o0.z = fmaxf(p1.x + bb0.z, 0.f);
        o0.w = fmaxf(p1.y + bb0.w, 0.f);
        o1.x = fmaxf(p2.x + bb1.x, 0.f);
        o1.y = fmaxf(p2.y + bb1.y, 0.f);
        o1.z = fmaxf(p3.x + bb1.z, 0.f);
        o1.w = fmaxf(p3.y + bb1.w, 0.f);
        float* cp = C + (size_t)(row0 + i) * HOUT + col0;
        *reinterpret_cast<float4*>(cp)     = o0;
        *reinterpret_cast<float4*>(cp + 4) = o1;
    }
}

// ---------------------------------------------------------------------------
extern "C" void kernel_launch(void* const* d_in, const int* in_sizes, int n_in,
                              void* d_out, int out_size) {
    const float* x     = (const float*)d_in[0];   // [N, 8, 512]
    const float* gamma = (const float*)d_in[1];   // [512]
    const float* beta  = (const float*)d_in[2];   // [512]
    const float* attnW = (const float*)d_in[3];   // [1024, 1]
    // d_in[4] = attn_b: constant across softmax axis -> cancels exactly.
    const float* outW  = (const float*)d_in[5];   // [512, 256]
    const float* outb  = (const float*)d_in[6];   // [256]
    float* out = (float*)d_out;                   // [N, 256]

    const int n = in_sizes[0] / (SEQ * HDIM);

    ln_attn_kernel<<<n, 256>>>(x, gamma, beta, attnW);

    dim3 grid(HOUT / BN, n / BM);
    gemm_relu_kernel<<<grid, 256>>>(outW, outb, out);
}

// round 3
// speedup vs baseline: 1.2338x; 1.2338x over previous
#include <cuda_runtime.h>
#include <cstdint>

#define SEQ     8
#define HDIM    512
#define HOUT    256
#define LN_EPS  1e-5f
#define MAX_ROWS 65536

// Scratch: fused (node + pooled) vectors, [N, 512], tf32-rounded fp32 bits.
__device__ float g_fused[(size_t)MAX_ROWS * HDIM];

// ---------------------------------------------------------------------------
// Helpers
// ---------------------------------------------------------------------------
__device__ __forceinline__ float warp_sum(float v) {
    #pragma unroll
    for (int o = 16; o; o >>= 1) v += __shfl_xor_sync(0xffffffffu, v, o);
    return v;
}

__device__ __forceinline__ uint32_t cvt_tf32(float f) {
    uint32_t u;
    asm("cvt.rna.tf32.f32 %0, %1;" : "=r"(u) : "f"(f));
    return u;
}

__device__ __forceinline__ void mma_tf32(float* d, const uint32_t* a, const uint32_t* b) {
    asm volatile(
        "mma.sync.aligned.m16n8k8.row.col.f32.tf32.tf32.f32 "
        "{%0,%1,%2,%3}, {%4,%5,%6,%7}, {%8,%9}, {%0,%1,%2,%3};"
        : "+f"(d[0]), "+f"(d[1]), "+f"(d[2]), "+f"(d[3])
        : "r"(a[0]), "r"(a[1]), "r"(a[2]), "r"(a[3]), "r"(b[0]), "r"(b[1]));
}

// ---------------------------------------------------------------------------
// Kernel A: LayerNorm (8 positions) + attention softmax pooling -> fused vec
// One CTA per row; warp w handles seq position w. Output tf32-rounded.
// ---------------------------------------------------------------------------
__global__ __launch_bounds__(256) void ln_attn_kernel(
    const float* __restrict__ x,
    const float* __restrict__ gamma,
    const float* __restrict__ beta,
    const float* __restrict__ attnW)
{
    __shared__ float s_y[SEQ][HDIM];
    __shared__ float s_logit[SEQ];

    const int row  = blockIdx.x;
    const int w    = threadIdx.x >> 5;
    const int lane = threadIdx.x & 31;

    const float4* xp = reinterpret_cast<const float4*>(
        x + (size_t)row * SEQ * HDIM + (size_t)w * HDIM);

    float4 v[4];
    float sum = 0.f, sq = 0.f;
    #pragma unroll
    for (int i = 0; i < 4; i++) {
        v[i] = xp[lane + i * 32];
        sum += v[i].x + v[i].y + v[i].z + v[i].w;
        sq  += v[i].x * v[i].x + v[i].y * v[i].y + v[i].z * v[i].z + v[i].w * v[i].w;
    }
    sum = warp_sum(sum);
    sq  = warp_sum(sq);
    const float mean = sum * (1.f / HDIM);
    const float var  = sq * (1.f / HDIM) - mean * mean;
    const float rstd = rsqrtf(var + LN_EPS);

    const float4* gp = reinterpret_cast<const float4*>(gamma);
    const float4* bp = reinterpret_cast<const float4*>(beta);
    const float4* wp = reinterpret_cast<const float4*>(attnW + (w == 0 ? 0 : HDIM));

    float dot = 0.f;
    #pragma unroll
    for (int i = 0; i < 4; i++) {
        const int idx = lane + i * 32;
        const float4 g  = __ldg(gp + idx);
        const float4 bb = __ldg(bp + idx);
        const float4 ww = __ldg(wp + idx);
        float4 y;
        y.x = (v[i].x - mean) * rstd * g.x + bb.x;
        y.y = (v[i].y - mean) * rstd * g.y + bb.y;
        y.z = (v[i].z - mean) * rstd * g.z + bb.z;
        y.w = (v[i].w - mean) * rstd * g.w + bb.w;
        dot += y.x * ww.x + y.y * ww.y + y.z * ww.z + y.w * ww.w;
        reinterpret_cast<float4*>(&s_y[w][0])[idx] = y;
    }
    dot = warp_sum(dot);
    if (lane == 0) s_logit[w] = dot;
    __syncthreads();

    // Softmax over 7 neighbor logits (node.W_t + attn_b cancels exactly).
    float l[7];
    float m = -1e30f;
    #pragma unroll
    for (int j = 0; j < 7; j++) { l[j] = s_logit[j + 1]; m = fmaxf(m, l[j]); }
    float s = 0.f;
    #pragma unroll
    for (int j = 0; j < 7; j++) { l[j] = __expf(l[j] - m); s += l[j]; }
    const float inv = 1.f / s;

    const int c = threadIdx.x * 2;
    float2 acc = *reinterpret_cast<const float2*>(&s_y[0][c]);
    #pragma unroll
    for (int j = 0; j < 7; j++) {
        const float a = l[j] * inv;
        const float2 yv = *reinterpret_cast<const float2*>(&s_y[j + 1][c]);
        acc.x += a * yv.x;
        acc.y += a * yv.y;
    }
    // tf32-round here so the GEMM A-path needs no conversion.
    float2 o;
    o.x = __uint_as_float(cvt_tf32(acc.x));
    o.y = __uint_as_float(cvt_tf32(acc.y));
    *reinterpret_cast<float2*>(&g_fused[(size_t)row * HDIM + c]) = o;
}

// ---------------------------------------------------------------------------
// Kernel B: C = relu(A @ B + bias) via mma.sync.m16n8k8.tf32
// CTA tile 128x64, 8 warps (4x2), warp tile 32x32, BK=32, double-buffered.
// A smem: K-major transposed [BK][128], stride 136 -> fragment LDS
// bank = (8*(lane&3) + (lane>>2) + const) % 32, conflict-free.
// B smem: [BK][64], stride 72 -> same conflict-free property.
// ---------------------------------------------------------------------------
#define BM 128
#define BN 64
#define BK 32
#define ASTR 136
#define BSTR 72
#define GEMM_SMEM ((2 * BK * ASTR + 2 * BK * BSTR) * 4)

__global__ __launch_bounds__(256, 2) void gemm_mma_kernel(
    const float* __restrict__ B,     // [512, 256] row-major
    const float* __restrict__ bias,  // [256]
    float* __restrict__ C)           // [M, 256]
{
    extern __shared__ float smem[];
    float* As = smem;                      // [2][BK][ASTR]
    float* Bs = smem + 2 * BK * ASTR;      // [2][BK][BSTR]

    const int tid  = threadIdx.x;
    const int wid  = tid >> 5;
    const int lane = tid & 31;
    const int warp_m = wid & 3;            // 0..3
    const int warp_n = wid >> 2;           // 0..1
    const int g  = lane >> 2;              // 0..7
    const int tg = lane & 3;               // 0..3

    const int bn = blockIdx.x;             // 0..3
    const int bm = blockIdx.y;

    const float* Ag = g_fused + (size_t)bm * BM * HDIM;
    const float* Bg = B + bn * BN;

    // Global-load assignment
    const int ar  = tid & 127;             // A row 0..127 (32 consecutive per warp)
    const int ac0 = (tid >> 7) * 16;       // k-half: 0 or 16
    const int bk  = tid >> 3;              // B k-row 0..31
    const int bn4 = (tid & 7) * 8;         // B col 0..56

    float4 pa[4];
    float4 pb[2];

    float acc[2][4][4];
    #pragma unroll
    for (int mt = 0; mt < 2; mt++)
        #pragma unroll
        for (int nt = 0; nt < 4; nt++)
            #pragma unroll
            for (int i = 0; i < 4; i++) acc[mt][nt][i] = 0.f;

    // --- prologue: load chunk 0 ---
    #pragma unroll
    for (int j = 0; j < 4; j++)
        pa[j] = *reinterpret_cast<const float4*>(Ag + (size_t)ar * HDIM + ac0 + j * 4);
    #pragma unroll
    for (int j = 0; j < 2; j++)
        pb[j] = *reinterpret_cast<const float4*>(Bg + (size_t)bk * HOUT + bn4 + j * 4);

    // STS chunk 0 into buffer 0
    {
        float* Ab = As;
        float* Bb = Bs;
        #pragma unroll
        for (int j = 0; j < 4; j++) {
            const int c = ac0 + j * 4;
            Ab[(c + 0) * ASTR + ar] = pa[j].x;
            Ab[(c + 1) * ASTR + ar] = pa[j].y;
            Ab[(c + 2) * ASTR + ar] = pa[j].z;
            Ab[(c + 3) * ASTR + ar] = pa[j].w;
        }
        #pragma unroll
        for (int j = 0; j < 2; j++) {
            float4 t;
            t.x = __uint_as_float(cvt_tf32(pb[j].x));
            t.y = __uint_as_float(cvt_tf32(pb[j].y));
            t.z = __uint_as_float(cvt_tf32(pb[j].z));
            t.w = __uint_as_float(cvt_tf32(pb[j].w));
            *reinterpret_cast<float4*>(Bb + bk * BSTR + bn4 + j * 4) = t;
        }
    }
    __syncthreads();

    #pragma unroll 1
    for (int k = 0; k < HDIM / BK; k++) {
        const int cur = k & 1;

        // prefetch next chunk (global -> regs)
        if (k < HDIM / BK - 1) {
            const int k0 = (k + 1) * BK;
            #pragma unroll
            for (int j = 0; j < 4; j++)
                pa[j] = *reinterpret_cast<const float4*>(Ag + (size_t)ar * HDIM + k0 + ac0 + j * 4);
            #pragma unroll
            for (int j = 0; j < 2; j++)
                pb[j] = *reinterpret_cast<const float4*>(Bg + (size_t)(k0 + bk) * HOUT + bn4 + j * 4);
        }

        // compute on buffer cur
        const float* Ab = As + cur * BK * ASTR;
        const float* Bb = Bs + cur * BK * BSTR;
        #pragma unroll
        for (int ks = 0; ks < 4; ks++) {
            uint32_t a[2][4], b[4][2];
            const int c = ks * 8 + tg;
            #pragma unroll
            for (int mt = 0; mt < 2; mt++) {
                const int r = warp_m * 32 + mt * 16 + g;
                a[mt][0] = __float_as_uint(Ab[c * ASTR + r]);
                a[mt][1] = __float_as_uint(Ab[c * ASTR + r + 8]);
                a[mt][2] = __float_as_uint(Ab[(c + 4) * ASTR + r]);
                a[mt][3] = __float_as_uint(Ab[(c + 4) * ASTR + r + 8]);
            }
            #pragma unroll
            for (int nt = 0; nt < 4; nt++) {
                const int n = warp_n * 32 + nt * 8 + g;
                b[nt][0] = __float_as_uint(Bb[c * BSTR + n]);
                b[nt][1] = __float_as_uint(Bb[(c + 4) * BSTR + n]);
            }
            #pragma unroll
            for (int mt = 0; mt < 2; mt++)
                #pragma unroll
                for (int nt = 0; nt < 4; nt++)
                    mma_tf32(acc[mt][nt], a[mt], b[nt]);
        }

        // stage next chunk (regs -> smem other buffer)
        if (k < HDIM / BK - 1) {
            __syncthreads();
            float* Ab2 = As + (cur ^ 1) * BK * ASTR;
            float* Bb2 = Bs + (cur ^ 1) * BK * BSTR;
            #pragma unroll
            for (int j = 0; j < 4; j++) {
                const int c2 = ac0 + j * 4;
                Ab2[(c2 + 0) * ASTR + ar] = pa[j].x;
                Ab2[(c2 + 1) * ASTR + ar] = pa[j].y;
                Ab2[(c2 + 2) * ASTR + ar] = pa[j].z;
                Ab2[(c2 + 3) * ASTR + ar] = pa[j].w;
            }
            #pragma unroll
            for (int j = 0; j < 2; j++) {
                float4 t;
                t.x = __uint_as_float(cvt_tf32(pb[j].x));
                t.y = __uint_as_float(cvt_tf32(pb[j].y));
                t.z = __uint_as_float(cvt_tf32(pb[j].z));
                t.w = __uint_as_float(cvt_tf32(pb[j].w));
                *reinterpret_cast<float4*>(Bb2 + bk * BSTR + bn4 + j * 4) = t;
            }
            __syncthreads();
        }
    }

    // Epilogue: bias + relu
    const int row_base = bm * BM + warp_m * 32;
    const int col_base = bn * BN + warp_n * 32;
    #pragma unroll
    for (int mt = 0; mt < 2; mt++) {
        #pragma unroll
        for (int nt = 0; nt < 4; nt++) {
            const int r0 = row_base + mt * 16 + g;
            const int c0 = col_base + nt * 8 + 2 * tg;
            const float2 bb = *reinterpret_cast<const float2*>(bias + c0);
            float2 o0, o1;
            o0.x = fmaxf(acc[mt][nt][0] + bb.x, 0.f);
            o0.y = fmaxf(acc[mt][nt][1] + bb.y, 0.f);
            o1.x = fmaxf(acc[mt][nt][2] + bb.x, 0.f);
            o1.y = fmaxf(acc[mt][nt][3] + bb.y, 0.f);
            *reinterpret_cast<float2*>(C + (size_t)r0 * HOUT + c0) = o0;
            *reinterpret_cast<float2*>(C + (size_t)(r0 + 8) * HOUT + c0) = o1;
        }
    }
}

// ---------------------------------------------------------------------------
extern "C" void kernel_launch(void* const* d_in, const int* in_sizes, int n_in,
                              void* d_out, int out_size) {
    const float* x     = (const float*)d_in[0];   // [N, 8, 512]
    const float* gamma = (const float*)d_in[1];   // [512]
    const float* beta  = (const float*)d_in[2];   // [512]
    const float* attnW = (const float*)d_in[3];   // [1024, 1]
    // d_in[4] = attn_b: constant across softmax axis -> cancels exactly.
    const float* outW  = (const float*)d_in[5];   // [512, 256]
    const float* outb  = (const float*)d_in[6];   // [256]
    float* out = (float*)d_out;                   // [N, 256]

    const int n = in_sizes[0] / (SEQ * HDIM);

    cudaFuncSetAttribute(gemm_mma_kernel,
                         cudaFuncAttributeMaxDynamicSharedMemorySize, GEMM_SMEM);

    ln_attn_kernel<<<n, 256>>>(x, gamma, beta, attnW);

    dim3 grid(HOUT / BN, n / BM);
    gemm_mma_kernel<<<grid, 256, GEMM_SMEM>>>(outW, outb, out);
}

// round 4
// speedup vs baseline: 1.5288x; 1.2391x over previous
#include <cuda_runtime.h>
#include <cstdint>

#define SEQ     8
#define HDIM    512
#define HOUT    256
#define LN_EPS  1e-5f
#define MAX_ROWS 65536

// Scratch: fused (node + pooled) vectors, [N, 512], tf32-rounded fp32 bits.
__device__ float g_fused[(size_t)MAX_ROWS * HDIM];
// Transposed + tf32-rounded out_W: [256, 512] (n-major, k-contiguous).
__device__ float g_Bt[(size_t)HOUT * HDIM];

// ---------------------------------------------------------------------------
// Helpers
// ---------------------------------------------------------------------------
__device__ __forceinline__ float warp_sum(float v) {
    #pragma unroll
    for (int o = 16; o; o >>= 1) v += __shfl_xor_sync(0xffffffffu, v, o);
    return v;
}

__device__ __forceinline__ uint32_t cvt_tf32(float f) {
    uint32_t u;
    asm("cvt.rna.tf32.f32 %0, %1;" : "=r"(u) : "f"(f));
    return u;
}

__device__ __forceinline__ uint32_t smem_u32(const void* p) {
    uint32_t a;
    asm("{ .reg .u64 t; cvta.to.shared.u64 t, %1; cvt.u32.u64 %0, t; }" : "=r"(a) : "l"(p));
    return a;
}

__device__ __forceinline__ void mma_tf32(float* d, const uint32_t* a, const uint32_t* b) {
    asm volatile(
        "mma.sync.aligned.m16n8k8.row.col.f32.tf32.tf32.f32 "
        "{%0,%1,%2,%3}, {%4,%5,%6,%7}, {%8,%9}, {%0,%1,%2,%3};"
        : "+f"(d[0]), "+f"(d[1]), "+f"(d[2]), "+f"(d[3])
        : "r"(a[0]), "r"(a[1]), "r"(a[2]), "r"(a[3]), "r"(b[0]), "r"(b[1]));
}

__device__ __forceinline__ void cp_async16(uint32_t dst, const void* src) {
    asm volatile("cp.async.cg.shared.global [%0], [%1], 16;"
                 :: "r"(dst), "l"(src) : "memory");
}
#define CP_COMMIT() asm volatile("cp.async.commit_group;" ::: "memory")
#define CP_WAIT(n)  asm volatile("cp.async.wait_group %0;" :: "n"(n) : "memory")

// ---------------------------------------------------------------------------
// Kernel A: LayerNorm (8 positions) + attention softmax pooling -> fused vec
// ---------------------------------------------------------------------------
__global__ __launch_bounds__(256) void ln_attn_kernel(
    const float* __restrict__ x,
    const float* __restrict__ gamma,
    const float* __restrict__ beta,
    const float* __restrict__ attnW)
{
    __shared__ float s_y[SEQ][HDIM];
    __shared__ float s_logit[SEQ];

    const int row  = blockIdx.x;
    const int w    = threadIdx.x >> 5;
    const int lane = threadIdx.x & 31;

    const float4* xp = reinterpret_cast<const float4*>(
        x + (size_t)row * SEQ * HDIM + (size_t)w * HDIM);

    float4 v[4];
    float sum = 0.f, sq = 0.f;
    #pragma unroll
    for (int i = 0; i < 4; i++) {
        v[i] = xp[lane + i * 32];
        sum += v[i].x + v[i].y + v[i].z + v[i].w;
        sq  += v[i].x * v[i].x + v[i].y * v[i].y + v[i].z * v[i].z + v[i].w * v[i].w;
    }
    sum = warp_sum(sum);
    sq  = warp_sum(sq);
    const float mean = sum * (1.f / HDIM);
    const float var  = sq * (1.f / HDIM) - mean * mean;
    const float rstd = rsqrtf(var + LN_EPS);

    const float4* gp = reinterpret_cast<const float4*>(gamma);
    const float4* bp = reinterpret_cast<const float4*>(beta);
    const float4* wp = reinterpret_cast<const float4*>(attnW + (w == 0 ? 0 : HDIM));

    float dot = 0.f;
    #pragma unroll
    for (int i = 0; i < 4; i++) {
        const int idx = lane + i * 32;
        const float4 g  = __ldg(gp + idx);
        const float4 bb = __ldg(bp + idx);
        const float4 ww = __ldg(wp + idx);
        float4 y;
        y.x = (v[i].x - mean) * rstd * g.x + bb.x;
        y.y = (v[i].y - mean) * rstd * g.y + bb.y;
        y.z = (v[i].z - mean) * rstd * g.z + bb.z;
        y.w = (v[i].w - mean) * rstd * g.w + bb.w;
        dot += y.x * ww.x + y.y * ww.y + y.z * ww.z + y.w * ww.w;
        reinterpret_cast<float4*>(&s_y[w][0])[idx] = y;
    }
    dot = warp_sum(dot);
    if (lane == 0) s_logit[w] = dot;
    __syncthreads();

    float l[7];
    float m = -1e30f;
    #pragma unroll
    for (int j = 0; j < 7; j++) { l[j] = s_logit[j + 1]; m = fmaxf(m, l[j]); }
    float s = 0.f;
    #pragma unroll
    for (int j = 0; j < 7; j++) { l[j] = __expf(l[j] - m); s += l[j]; }
    const float inv = 1.f / s;

    const int c = threadIdx.x * 2;
    float2 acc = *reinterpret_cast<const float2*>(&s_y[0][c]);
    #pragma unroll
    for (int j = 0; j < 7; j++) {
        const float a = l[j] * inv;
        const float2 yv = *reinterpret_cast<const float2*>(&s_y[j + 1][c]);
        acc.x += a * yv.x;
        acc.y += a * yv.y;
    }
    float2 o;
    o.x = __uint_as_float(cvt_tf32(acc.x));
    o.y = __uint_as_float(cvt_tf32(acc.y));
    *reinterpret_cast<float2*>(&g_fused[(size_t)row * HDIM + c]) = o;
}

// ---------------------------------------------------------------------------
// Transpose out_W [512,256] -> g_Bt [256,512], tf32-rounded.
// ---------------------------------------------------------------------------
__global__ __launch_bounds__(256) void transpose_B_kernel(const float* __restrict__ B) {
    __shared__ float tile[32][33];
    const int n0 = blockIdx.x * 32;
    const int k0 = blockIdx.y * 32;
    const int tx = threadIdx.x & 31;
    const int ty = threadIdx.x >> 5;   // 0..7
    #pragma unroll
    for (int i = 0; i < 32; i += 8)
        tile[ty + i][tx] = B[(size_t)(k0 + ty + i) * HOUT + n0 + tx];
    __syncthreads();
    #pragma unroll
    for (int i = 0; i < 32; i += 8) {
        float v = tile[tx][ty + i];
        g_Bt[(size_t)(n0 + ty + i) * HDIM + k0 + tx] = __uint_as_float(cvt_tf32(v));
    }
}

// ---------------------------------------------------------------------------
// Kernel B: C = relu(A @ Bt^T + bias) via mma.sync.m16n8k8.tf32.
// CTA 128x128, BK=32, 3-stage cp.async pipeline.
// 8 warps as 4x2; warp tile 32x64 (mt=2, nt=8).
// Vectorized fragments via k-permutation: each LDS.128 of 4 consecutive k's
// feeds 2 mma k-groups; both A and B use the same permutation.
// Swizzle on 16B units: unit = row*8 + (u ^ ((row&1)*4))  -> conflict-free.
// ---------------------------------------------------------------------------
#define BM 128
#define BN 128
#define BK 32
#define STAGES 3
#define A_STAGE_FLOATS (BM * BK)                   // 4096 floats = 16 KB
#define B_STAGE_FLOATS (BN * BK)                   // 16 KB
#define STAGE_FLOATS   (A_STAGE_FLOATS + B_STAGE_FLOATS)
#define GEMM_SMEM      (STAGES * STAGE_FLOATS * 4) // 96 KB

__device__ __forceinline__ int swz_unit(int row, int u) {
    return row * 8 + (u ^ ((row & 1) << 2));
}

__global__ __launch_bounds__(256, 2) void gemm_v3_kernel(
    const float* __restrict__ bias,
    float* __restrict__ C)
{
    extern __shared__ float smem[];

    const int tid  = threadIdx.x;
    const int wid  = tid >> 5;
    const int lane = tid & 31;
    const int warp_m = wid & 3;            // 0..3 -> M offset *32
    const int warp_n = wid >> 2;           // 0..1 -> N offset *64
    const int g  = lane >> 2;              // 0..7
    const int tg = lane & 3;               // 0..3

    const int bn = blockIdx.x;             // 0..1
    const int bm = blockIdx.y;             // 0..511

    const float* Ag = g_fused + (size_t)bm * BM * HDIM;
    const float* Bg = g_Bt + (size_t)bn * BN * HDIM;

    const uint32_t smem_base = smem_u32(smem);

    // cp.async staging assignment: thread t covers row t>>1, units (t&1)*4 + j
    const int st_row = tid >> 1;
    const int st_ub  = (tid & 1) * 4;

    float acc[2][8][4];
    #pragma unroll
    for (int mt = 0; mt < 2; mt++)
        #pragma unroll
        for (int nt = 0; nt < 8; nt++)
            #pragma unroll
            for (int i = 0; i < 4; i++) acc[mt][nt][i] = 0.f;

    // --- stage one chunk into pipeline slot 'st' ---
    auto stage_chunk = [&](int kchunk, int st) {
        const uint32_t sA = smem_base + (uint32_t)(st * STAGE_FLOATS) * 4u;
        const uint32_t sB = sA + A_STAGE_FLOATS * 4u;
        const float* srcA = Ag + (size_t)st_row * HDIM + kchunk * BK + st_ub * 4;
        const float* srcB = Bg + (size_t)st_row * HDIM + kchunk * BK + st_ub * 4;
        #pragma unroll
        for (int j = 0; j < 4; j++) {
            const int uA = st_ub + j;
            cp_async16(sA + (uint32_t)swz_unit(st_row, uA) * 16u, srcA + j * 4);
        }
        #pragma unroll
        for (int j = 0; j < 4; j++) {
            const int uB = st_ub + j;
            cp_async16(sB + (uint32_t)swz_unit(st_row, uB) * 16u, srcB + j * 4);
        }
    };

    // Prologue: fill the pipeline.
    #pragma unroll
    for (int s = 0; s < STAGES; s++) {
        stage_chunk(s, s);
        CP_COMMIT();
    }

    const int NCH = HDIM / BK;   // 16
    #pragma unroll 1
    for (int k = 0; k < NCH; k++) {
        const int cur = k % STAGES;
        CP_WAIT(STAGES - 1);
        __syncthreads();

        const float* Abuf = smem + cur * STAGE_FLOATS;
        const float* Bbuf = Abuf + A_STAGE_FLOATS;

        #pragma unroll
        for (int s = 0; s < 2; s++) {           // two 16-k slabs
            // A fragments: 4 x LDS.128
            uint32_t af[4][4];                   // [mt*2 + h][4]
            #pragma unroll
            for (int mt = 0; mt < 2; mt++) {
                #pragma unroll
                for (int h = 0; h < 2; h++) {
                    const int r = warp_m * 32 + mt * 16 + g + h * 8;
                    const float4 v = *reinterpret_cast<const float4*>(
                        Abuf + swz_unit(r, s * 4 + tg) * 4);
                    af[mt * 2 + h][0] = __float_as_uint(v.x);
                    af[mt * 2 + h][1] = __float_as_uint(v.y);
                    af[mt * 2 + h][2] = __float_as_uint(v.z);
                    af[mt * 2 + h][3] = __float_as_uint(v.w);
                }
            }
            #pragma unroll
            for (int half = 0; half < 2; half++) {
                uint32_t bf[4][4];
                #pragma unroll
                for (int q = 0; q < 4; q++) {
                    const int n = warp_n * 64 + (half * 4 + q) * 8 + g;
                    const float4 v = *reinterpret_cast<const float4*>(
                        Bbuf + swz_unit(n, s * 4 + tg) * 4);
                    bf[q][0] = __float_as_uint(v.x);
                    bf[q][1] = __float_as_uint(v.y);
                    bf[q][2] = __float_as_uint(v.z);
                    bf[q][3] = __float_as_uint(v.w);
                }
                #pragma unroll
                for (int mt = 0; mt < 2; mt++) {
                    #pragma unroll
                    for (int q = 0; q < 4; q++) {
                        const int nt = half * 4 + q;
                        // k-group 0: (x, y) slots
                        uint32_t a0[4] = { af[mt*2][0], af[mt*2+1][0],
                                           af[mt*2][1], af[mt*2+1][1] };
                        uint32_t b0[2] = { bf[q][0], bf[q][1] };
                        mma_tf32(acc[mt][nt], a0, b0);
                        // k-group 1: (z, w) slots
                        uint32_t a1[4] = { af[mt*2][2], af[mt*2+1][2],
                                           af[mt*2][3], af[mt*2+1][3] };
                        uint32_t b1[2] = { bf[q][2], bf[q][3] };
                        mma_tf32(acc[mt][nt], a1, b1);
                    }
                }
            }
        }

        __syncthreads();
        if (k + STAGES < NCH) stage_chunk(k + STAGES, cur);
        CP_COMMIT();
    }

    // Epilogue: bias + relu.
    const int row_base = bm * BM + warp_m * 32;
    const int col_base = bn * BN + warp_n * 64;
    #pragma unroll
    for (int mt = 0; mt < 2; mt++) {
        #pragma unroll
        for (int nt = 0; nt < 8; nt++) {
            const int r0 = row_base + mt * 16 + g;
            const int c0 = col_base + nt * 8 + 2 * tg;
            const float2 bb = *reinterpret_cast<const float2*>(bias + c0);
            float2 o0, o1;
            o0.x = fmaxf(acc[mt][nt][0] + bb.x, 0.f);
            o0.y = fmaxf(acc[mt][nt][1] + bb.y, 0.f);
            o1.x = fmaxf(acc[mt][nt][2] + bb.x, 0.f);
            o1.y = fmaxf(acc[mt][nt][3] + bb.y, 0.f);
            *reinterpret_cast<float2*>(C + (size_t)r0 * HOUT + c0) = o0;
            *reinterpret_cast<float2*>(C + (size_t)(r0 + 8) * HOUT + c0) = o1;
        }
    }
}

// ---------------------------------------------------------------------------
extern "C" void kernel_launch(void* const* d_in, const int* in_sizes, int n_in,
                              void* d_out, int out_size) {
    const float* x     = (const float*)d_in[0];   // [N, 8, 512]
    const float* gamma = (const float*)d_in[1];   // [512]
    const float* beta  = (const float*)d_in[2];   // [512]
    const float* attnW = (const float*)d_in[3];   // [1024, 1]
    // d_in[4] = attn_b: constant across softmax axis -> cancels exactly.
    const float* outW  = (const float*)d_in[5];   // [512, 256]
    const float* outb  = (const float*)d_in[6];   // [256]
    float* out = (float*)d_out;                   // [N, 256]

    const int n = in_sizes[0] / (SEQ * HDIM);

    cudaFuncSetAttribute(gemm_v3_kernel,
                         cudaFuncAttributeMaxDynamicSharedMemorySize, GEMM_SMEM);

    ln_attn_kernel<<<n, 256>>>(x, gamma, beta, attnW);
    transpose_B_kernel<<<dim3(HOUT / 32, HDIM / 32), 256>>>(outW);

    dim3 grid(HOUT / BN, n / BM);
    gemm_v3_kernel<<<grid, 256, GEMM_SMEM>>>(outb, out);
}